// round 9
// baseline (speedup 1.0000x reference)
#include <cuda_runtime.h>
#include <cuda_fp16.h>
#include <cstdint>

// Problem constants
#define NTOK   4096
#define DM     1024
#define HID    4096
#define NEXP   8
#define NPAIRS (NTOK*2)      // 8192 (token, k) pairs

// ---------------- scratch (allocation-free __device__ globals) ----------------
__device__ __half g_xgh[(size_t)NPAIRS * DM];       // gathered activations (fp16)
__device__ __half g_h  [(size_t)NPAIRS * HID];      // hidden per slot (fp16)
__device__ float  g_y  [(size_t)NPAIRS * DM];       // expert outputs (fp32)
__device__ int    g_tok_e[NPAIRS];
__device__ float  g_tok_w[NPAIRS];
__device__ int    g_tok_slot[NPAIRS];
__device__ int    g_pair_tok[NPAIRS];
__device__ int    g_cnt[NEXP];
__device__ int    g_off[NEXP];
__device__ int    g_cur[NEXP];

// ---------------- portable PTX helpers ----------------
__device__ __forceinline__ uint32_t smem_u32(const void* p) {
    uint32_t a;
    asm("{ .reg .u64 t; cvta.to.shared.u64 t, %1; cvt.u32.u64 %0, t; }" : "=r"(a) : "l"(p));
    return a;
}
__device__ __forceinline__ void ldsm_x4(uint32_t* r, uint32_t addr) {
    asm volatile("ldmatrix.sync.aligned.m8n8.x4.shared.b16 {%0,%1,%2,%3}, [%4];"
        : "=r"(r[0]), "=r"(r[1]), "=r"(r[2]), "=r"(r[3]) : "r"(addr));
}
__device__ __forceinline__ void mma_f16(float* c, const uint32_t* a, const uint32_t* b) {
    asm volatile("mma.sync.aligned.m16n8k16.row.col.f32.f16.f16.f32 "
        "{%0,%1,%2,%3}, {%4,%5,%6,%7}, {%8,%9}, {%0,%1,%2,%3};"
        : "+f"(c[0]), "+f"(c[1]), "+f"(c[2]), "+f"(c[3])
        : "r"(a[0]), "r"(a[1]), "r"(a[2]), "r"(a[3]), "r"(b[0]), "r"(b[1]));
}
__device__ __forceinline__ void cp16(uint32_t saddr, const void* g, bool pred) {
    int sz = pred ? 16 : 0;
    asm volatile("cp.async.cg.shared.global [%0], [%1], 16, %2;"
                 :: "r"(saddr), "l"(g), "r"(sz));
}
#define CP_COMMIT() asm volatile("cp.async.commit_group;" ::: "memory")
#define CP_WAIT(n)  asm volatile("cp.async.wait_group %0;" :: "n"(n) : "memory")

// ---------------- tiny routing kernels ----------------
__global__ void k_zero() { if (threadIdx.x < NEXP) g_cnt[threadIdx.x] = 0; }

__global__ void k_router(const float* __restrict__ x, const float* __restrict__ gw) {
    int t = (blockIdx.x * blockDim.x + threadIdx.x) >> 5;
    int lane = threadIdx.x & 31;
    if (t >= NTOK) return;
    const float4* xr = (const float4*)(x + (size_t)t * DM);
    const float4* g4 = (const float4*)gw;
    float s[NEXP];
    #pragma unroll
    for (int e = 0; e < NEXP; e++) s[e] = 0.f;
    #pragma unroll
    for (int j = 0; j < DM / 4 / 32; j++) {
        int idx = lane + j * 32;
        float4 xv = xr[idx];
        #pragma unroll
        for (int e = 0; e < NEXP; e++) {
            float4 wv = g4[e * (DM / 4) + idx];
            s[e] += xv.x * wv.x + xv.y * wv.y + xv.z * wv.z + xv.w * wv.w;
        }
    }
    #pragma unroll
    for (int e = 0; e < NEXP; e++)
        #pragma unroll
        for (int o = 16; o; o >>= 1) s[e] += __shfl_xor_sync(0xffffffffu, s[e], o);
    if (lane == 0) {
        float mx = s[0];
        #pragma unroll
        for (int e = 1; e < NEXP; e++) mx = fmaxf(mx, s[e]);
        float p[NEXP], den = 0.f;
        #pragma unroll
        for (int e = 0; e < NEXP; e++) { p[e] = expf(s[e] - mx); den += p[e]; }
        float inv = 1.f / den;
        int m0 = 0;
        #pragma unroll
        for (int e = 1; e < NEXP; e++) if (p[e] > p[m0]) m0 = e;
        int m1 = (m0 == 0) ? 1 : 0;
        #pragma unroll
        for (int e = 0; e < NEXP; e++) if (e != m0 && p[e] > p[m1]) m1 = e;
        g_tok_e[t * 2 + 0] = m0;  g_tok_e[t * 2 + 1] = m1;
        g_tok_w[t * 2 + 0] = p[m0] * inv;  g_tok_w[t * 2 + 1] = p[m1] * inv;
        atomicAdd(&g_cnt[m0], 1);  atomicAdd(&g_cnt[m1], 1);
    }
}

__global__ void k_scan() {
    if (threadIdx.x == 0) {
        int acc = 0;
        for (int e = 0; e < NEXP; e++) { g_off[e] = acc; acc += g_cnt[e]; g_cur[e] = 0; }
    }
}

__global__ void k_slot() {
    int p = blockIdx.x * blockDim.x + threadIdx.x;
    if (p >= NPAIRS) return;
    int e = g_tok_e[p];
    int slot = g_off[e] + atomicAdd(&g_cur[e], 1);
    g_pair_tok[slot] = p >> 1;
    g_tok_slot[p] = slot;
}

// gather + convert x rows to fp16
__global__ void k_gather(const float* __restrict__ x) {
    int slot = blockIdx.x;
    int tok = g_pair_tok[slot];
    int d4 = threadIdx.x * 4;
    float4 v = *(const float4*)(x + (size_t)tok * DM + d4);
    __half2 h[2] = {__floats2half2_rn(v.x, v.y), __floats2half2_rn(v.z, v.w)};
    *(uint2*)(g_xgh + (size_t)slot * DM + d4) = *(uint2*)h;
}

// ---------------- fp16 mma.sync grouped GEMM (BK=32), fused fp32->fp16 B cvt ----------------
// CTA BM=128 x BN x 32, 8 warps (2M x 4N), warp tile 64 x (BN/4), occ 2.
// A fp16: 3-stage cp.async ring. B fp32 weights: LDG.128 prefetch -> cvt -> STS 2-buf ring.
#define BM 128
#define BK 32
#define ASTG 3
#define PITCH 80                          // 32 halves = 64B data + 16B pad
#define A_BYTES (BM * PITCH)              // 10240
#define BOFF    (ASTG * A_BYTES)          // 30720

template<int KTOT, int BN, bool RELU, typename OutT>
__global__ void __launch_bounds__(256, 2)
k_gemm(const __half* __restrict__ A,      // [slots, KTOT] fp16
       const float* __restrict__ B32,     // [NEXP*n_total, KTOT] fp32 weights
       const float* __restrict__ bias,
       OutT* __restrict__ C,              // [slots, n_total]
       int n_total) {
    constexpr int NC = KTOT / BK;
    constexpr int TN = BN / 4;            // warp N tile (4 warps in N)
    constexpr int BF = TN / 16;           // B ldsm.x4 frags per warp
    constexpr int NN = TN / 8;            // mma N steps
    constexpr int B_BYTES = BN * PITCH;
    constexpr int NBT = BN * 2;           // B loader tasks (16 floats each)

    int e = blockIdx.z;
    int cnt = g_cnt[e];
    int m0 = blockIdx.y * BM;
    if (m0 >= cnt) return;
    int base = g_off[e];
    int n0 = blockIdx.x * BN;
    int mrem = cnt - m0;

    extern __shared__ char smc[];
    uint32_t sb = smem_u32(smc);
    int tid = threadIdx.x;
    int wid = tid >> 5, lane = tid & 31;
    int gp = lane >> 2, tg = lane & 3;
    int wm = (wid & 1) * 64;          // warp M offset
    int wn = (wid >> 1) * TN;         // warp N offset

    const __half* Ab = A + (size_t)(base + m0) * KTOT;
    const float* Bb = B32 + ((size_t)e * n_total + n0) * KTOT;

    // A loader (cp.async): 512 16B tasks, 2/thread. row = t>>2, chunk = t&3
    int ar0 = tid >> 2, ac0 = tid & 3;
    int ar1 = (tid + 256) >> 2, ac1 = (tid + 256) & 3;
    auto loadA = [&](int c, int stg) {
        int k0 = c * BK;
        cp16(sb + stg * A_BYTES + ar0 * PITCH + ac0 * 16,
             Ab + (size_t)ar0 * KTOT + k0 + ac0 * 8, ar0 < mrem);
        cp16(sb + stg * A_BYTES + ar1 * PITCH + ac1 * 16,
             Ab + (size_t)ar1 * KTOT + k0 + ac1 * 8, ar1 < mrem);
    };

    // B loader: BN rows x 32 floats; 2 threads/row, 16 floats each (tid < NBT active)
    float4 breg[4];
    int blr = tid >> 1, blc = tid & 1;
    bool bact = (NBT >= 256) || (tid < NBT);
    auto ldgB = [&](int c) {
        if (bact) {
            const float* p = Bb + (size_t)blr * KTOT + c * BK + blc * 16;
            breg[0] = __ldg((const float4*)p);
            breg[1] = __ldg((const float4*)(p + 4));
            breg[2] = __ldg((const float4*)(p + 8));
            breg[3] = __ldg((const float4*)(p + 12));
        }
    };
    auto stsB = [&](int buf) {
        if (bact) {
            __half2 h[8];
            #pragma unroll
            for (int i = 0; i < 4; i++) {
                h[i * 2 + 0] = __floats2half2_rn(breg[i].x, breg[i].y);
                h[i * 2 + 1] = __floats2half2_rn(breg[i].z, breg[i].w);
            }
            char* d = smc + BOFF + buf * B_BYTES + blr * PITCH + blc * 32;
            *(uint4*)d = *(uint4*)h;
            *(uint4*)(d + 16) = *(uint4*)(h + 4);
        }
    };

    // per-lane ldmatrix offsets (k-sub step adds ks*32 bytes)
    int m4 = lane >> 3, ri = lane & 7;
    uint32_t a_off[4], b_off[BF];
    #pragma unroll
    for (int mi = 0; mi < 4; mi++)
        a_off[mi] = (uint32_t)((wm + mi * 16 + (m4 & 1) * 8 + ri) * PITCH + (m4 >> 1) * 16);
    #pragma unroll
    for (int nj = 0; nj < BF; nj++)
        b_off[nj] = (uint32_t)(BOFF + (wn + nj * 16 + (m4 >> 1) * 8 + ri) * PITCH + (m4 & 1) * 16);

    float acc[4][NN][4];
    #pragma unroll
    for (int i = 0; i < 4; i++)
        #pragma unroll
        for (int j = 0; j < NN; j++)
            #pragma unroll
            for (int q = 0; q < 4; q++) acc[i][j][q] = 0.f;

    // prologue
    ldgB(0);
    #pragma unroll
    for (int s = 0; s < ASTG - 1; s++) { loadA(s, s); CP_COMMIT(); }
    stsB(0);
    ldgB(1);

    #pragma unroll 1
    for (int c = 0; c < NC; c++) {
        CP_WAIT(ASTG - 2);
        __syncthreads();                       // A stage c ready; B buf (c&1) visible

        if (c + ASTG - 1 < NC) loadA(c + ASTG - 1, (c + ASTG - 1) % ASTG);
        CP_COMMIT();

        uint32_t ast = sb + (c % ASTG) * A_BYTES;
        uint32_t bst = (c & 1) * B_BYTES;

        #pragma unroll
        for (int ks = 0; ks < 2; ks++) {       // two k16 sub-steps, frags reused
            uint32_t af[4][4], bf[BF][4];
            #pragma unroll
            for (int mi = 0; mi < 4; mi++) ldsm_x4(af[mi], ast + a_off[mi] + ks * 32);
            #pragma unroll
            for (int nj = 0; nj < BF; nj++) ldsm_x4(bf[nj], sb + bst + b_off[nj] + ks * 32);
            #pragma unroll
            for (int mi = 0; mi < 4; mi++)
                #pragma unroll
                for (int ni = 0; ni < NN; ni++)
                    mma_f16(acc[mi][ni], af[mi], &bf[ni >> 1][(ni & 1) * 2]);
        }

        if (c + 1 < NC) stsB((c + 1) & 1);     // cvt+store B for next iter
        if (c + 2 < NC) ldgB(c + 2);           // prefetch B fp32 (~1 iter cover)
    }

    // epilogue: bias (+relu), store
    const float* brow = bias + (size_t)e * n_total + n0;
    #pragma unroll
    for (int ni = 0; ni < NN; ni++) {
        int col = wn + ni * 8 + tg * 2;
        float b0 = brow[col], b1 = brow[col + 1];
        #pragma unroll
        for (int mi = 0; mi < 4; mi++) {
            int r0 = wm + mi * 16 + gp;
            float v0 = acc[mi][ni][0] + b0, v1 = acc[mi][ni][1] + b1;
            float v2 = acc[mi][ni][2] + b0, v3 = acc[mi][ni][3] + b1;
            if (RELU) {
                v0 = fmaxf(v0, 0.f); v1 = fmaxf(v1, 0.f);
                v2 = fmaxf(v2, 0.f); v3 = fmaxf(v3, 0.f);
            }
            if (r0 < mrem) {
                OutT* cr = C + (size_t)(base + m0 + r0) * n_total + n0 + col;
                if constexpr (sizeof(OutT) == 2) {
                    *(__half2*)cr = __floats2half2_rn(v0, v1);
                } else { cr[0] = v0; cr[1] = v1; }
            }
            if (r0 + 8 < mrem) {
                OutT* cr = C + (size_t)(base + m0 + r0 + 8) * n_total + n0 + col;
                if constexpr (sizeof(OutT) == 2) {
                    *(__half2*)cr = __floats2half2_rn(v2, v3);
                } else { cr[0] = v2; cr[1] = v3; }
            }
        }
    }
}

// out[t] = w0 * y[slot0] + w1 * y[slot1]
__global__ void k_combine(float* __restrict__ out) {
    int t = blockIdx.x;
    int d4 = threadIdx.x * 4;
    int s0 = g_tok_slot[t * 2 + 0], s1 = g_tok_slot[t * 2 + 1];
    float w0 = g_tok_w[t * 2 + 0],  w1 = g_tok_w[t * 2 + 1];
    float4 y0 = *(const float4*)(g_y + (size_t)s0 * DM + d4);
    float4 y1 = *(const float4*)(g_y + (size_t)s1 * DM + d4);
    float4 r;
    r.x = w0 * y0.x + w1 * y1.x;  r.y = w0 * y0.y + w1 * y1.y;
    r.z = w0 * y0.z + w1 * y1.z;  r.w = w0 * y0.w + w1 * y1.w;
    *(float4*)(out + (size_t)t * DM + d4) = r;
}

// ---------------- launch ----------------
// GEMM1: BN=128 -> smem = 30720 + 2*10240 = 51200
// GEMM2: BN=64  -> smem = 30720 + 2*5120  = 40960
#define SMEM1 (BOFF + 2 * 128 * PITCH)
#define SMEM2 (BOFF + 2 * 64 * PITCH)

extern "C" void kernel_launch(void* const* d_in, const int* in_sizes, int n_in,
                              void* d_out, int out_size) {
    const float* x  = (const float*)d_in[0];
    const float* gw = (const float*)d_in[1];
    const float* w1 = (const float*)d_in[2];
    const float* b1 = (const float*)d_in[3];
    const float* w2 = (const float*)d_in[4];
    const float* b2 = (const float*)d_in[5];
    float* out = (float*)d_out;

    cudaFuncSetAttribute((const void*)k_gemm<DM, 128, true, __half>,
                         cudaFuncAttributeMaxDynamicSharedMemorySize, SMEM1);
    cudaFuncSetAttribute((const void*)k_gemm<HID, 64, false, float>,
                         cudaFuncAttributeMaxDynamicSharedMemorySize, SMEM2);

    __half* xgh; cudaGetSymbolAddress((void**)&xgh, g_xgh);
    __half* hh;  cudaGetSymbolAddress((void**)&hh,  g_h);
    float*  yy;  cudaGetSymbolAddress((void**)&yy,  g_y);

    k_zero<<<1, 32>>>();
    k_router<<<NTOK / 8, 256>>>(x, gw);
    k_scan<<<1, 32>>>();
    k_slot<<<NPAIRS / 256, 256>>>();
    k_gather<<<NPAIRS, 256>>>(x);
    // GEMM1: [slots,1024]h x w1[e][4096,1024]^T (fp32, fused cvt) -> g_h fp16, bias+relu
    k_gemm<DM, 128, true, __half>
        <<<dim3(HID / 128, NPAIRS / BM, NEXP), 256, SMEM1>>>(xgh, w1, b1, hh, HID);
    // GEMM2: [slots,4096]h x w2[e][1024,4096]^T (fp32, fused cvt) -> g_y fp32, bias
    k_gemm<HID, 64, false, float>
        <<<dim3(DM / 64, NPAIRS / BM, NEXP), 256, SMEM2>>>(hh, w2, b2, yy, DM);
    k_combine<<<NTOK, 256>>>(out);
}

// round 10
// speedup vs baseline: 1.2088x; 1.2088x over previous
#include <cuda_runtime.h>
#include <cuda_fp16.h>
#include <cstdint>

// Problem constants
#define NTOK   4096
#define DM     1024
#define HID    4096
#define NEXP   8
#define NPAIRS (NTOK*2)      // 8192 (token, k) pairs

// ---------------- scratch (allocation-free __device__ globals) ----------------
__device__ __half g_xgh[(size_t)NPAIRS * DM];       // gathered activations (fp16)
__device__ __half g_h  [(size_t)NPAIRS * HID];      // hidden per slot (fp16)
__device__ float  g_y  [(size_t)NPAIRS * DM];       // expert outputs (fp32)
__device__ int    g_tok_e[NPAIRS];
__device__ float  g_tok_w[NPAIRS];
__device__ int    g_tok_slot[NPAIRS];
__device__ int    g_pair_tok[NPAIRS];
__device__ int    g_cnt[NEXP];
__device__ int    g_off[NEXP];
__device__ int    g_cur[NEXP];

// ---------------- portable PTX helpers ----------------
__device__ __forceinline__ uint32_t smem_u32(const void* p) {
    uint32_t a;
    asm("{ .reg .u64 t; cvta.to.shared.u64 t, %1; cvt.u32.u64 %0, t; }" : "=r"(a) : "l"(p));
    return a;
}
__device__ __forceinline__ void ldsm_x4(uint32_t* r, uint32_t addr) {
    asm volatile("ldmatrix.sync.aligned.m8n8.x4.shared.b16 {%0,%1,%2,%3}, [%4];"
        : "=r"(r[0]), "=r"(r[1]), "=r"(r[2]), "=r"(r[3]) : "r"(addr));
}
__device__ __forceinline__ void mma_f16(float* c, const uint32_t* a, const uint32_t* b) {
    asm volatile("mma.sync.aligned.m16n8k16.row.col.f32.f16.f16.f32 "
        "{%0,%1,%2,%3}, {%4,%5,%6,%7}, {%8,%9}, {%0,%1,%2,%3};"
        : "+f"(c[0]), "+f"(c[1]), "+f"(c[2]), "+f"(c[3])
        : "r"(a[0]), "r"(a[1]), "r"(a[2]), "r"(a[3]), "r"(b[0]), "r"(b[1]));
}
__device__ __forceinline__ void cp16(uint32_t saddr, const void* g, bool pred) {
    int sz = pred ? 16 : 0;
    asm volatile("cp.async.cg.shared.global [%0], [%1], 16, %2;"
                 :: "r"(saddr), "l"(g), "r"(sz));
}
#define CP_COMMIT() asm volatile("cp.async.commit_group;" ::: "memory")
#define CP_WAIT(n)  asm volatile("cp.async.wait_group %0;" :: "n"(n) : "memory")

// ---------------- routing kernels (fused) ----------------
// router: logits -> softmax -> top2 (no global atomics)
__global__ void k_router(const float* __restrict__ x, const float* __restrict__ gw) {
    int t = (blockIdx.x * blockDim.x + threadIdx.x) >> 5;
    int lane = threadIdx.x & 31;
    if (t >= NTOK) return;
    const float4* xr = (const float4*)(x + (size_t)t * DM);
    const float4* g4 = (const float4*)gw;
    float s[NEXP];
    #pragma unroll
    for (int e = 0; e < NEXP; e++) s[e] = 0.f;
    #pragma unroll
    for (int j = 0; j < DM / 4 / 32; j++) {
        int idx = lane + j * 32;
        float4 xv = xr[idx];
        #pragma unroll
        for (int e = 0; e < NEXP; e++) {
            float4 wv = g4[e * (DM / 4) + idx];
            s[e] += xv.x * wv.x + xv.y * wv.y + xv.z * wv.z + xv.w * wv.w;
        }
    }
    #pragma unroll
    for (int e = 0; e < NEXP; e++)
        #pragma unroll
        for (int o = 16; o; o >>= 1) s[e] += __shfl_xor_sync(0xffffffffu, s[e], o);
    if (lane == 0) {
        float mx = s[0];
        #pragma unroll
        for (int e = 1; e < NEXP; e++) mx = fmaxf(mx, s[e]);
        float p[NEXP], den = 0.f;
        #pragma unroll
        for (int e = 0; e < NEXP; e++) { p[e] = expf(s[e] - mx); den += p[e]; }
        float inv = 1.f / den;
        int m0 = 0;
        #pragma unroll
        for (int e = 1; e < NEXP; e++) if (p[e] > p[m0]) m0 = e;
        int m1 = (m0 == 0) ? 1 : 0;
        #pragma unroll
        for (int e = 0; e < NEXP; e++) if (e != m0 && p[e] > p[m1]) m1 = e;
        g_tok_e[t * 2 + 0] = m0;  g_tok_e[t * 2 + 1] = m1;
        g_tok_w[t * 2 + 0] = p[m0] * inv;  g_tok_w[t * 2 + 1] = p[m1] * inv;
    }
}

// single-block histogram + prefix (replaces k_zero + router atomics + scan)
__global__ void k_scan() {
    __shared__ int h[NEXP];
    int tid = threadIdx.x;
    if (tid < NEXP) h[tid] = 0;
    __syncthreads();
    for (int p = tid; p < NPAIRS; p += 256) atomicAdd(&h[g_tok_e[p]], 1);
    __syncthreads();
    if (tid == 0) {
        int acc = 0;
        for (int e = 0; e < NEXP; e++) {
            g_cnt[e] = h[e]; g_off[e] = acc; acc += h[e]; g_cur[e] = 0;
        }
    }
}

// fused slot-assignment + gather (block per pair)
__global__ void k_slotgather(const float* __restrict__ x) {
    __shared__ int s_slot;
    int p = blockIdx.x;
    if (threadIdx.x == 0) {
        int e = g_tok_e[p];
        int slot = g_off[e] + atomicAdd(&g_cur[e], 1);
        g_pair_tok[slot] = p >> 1;
        g_tok_slot[p] = slot;
        s_slot = slot;
    }
    __syncthreads();
    int slot = s_slot;
    int d4 = threadIdx.x * 4;
    float4 v = *(const float4*)(x + (size_t)(p >> 1) * DM + d4);
    __half2 h[2] = {__floats2half2_rn(v.x, v.y), __floats2half2_rn(v.z, v.w)};
    *(uint2*)(g_xgh + (size_t)slot * DM + d4) = *(uint2*)h;
}

// ---------------- fp16 mma.sync grouped GEMM (BK=32), fused fp32->fp16 B cvt ----------------
// R8-proven geometry: CTA 128x128x32, 8 warps (2M x 4N), warp 64x32, occ 2.
// A fp16: 3-stage cp.async ring. B fp32 weights: LDG.128 prefetch -> cvt -> STS 2-buf ring.
#define BM 128
#define BN 128
#define BK 32
#define ASTG 3
#define PITCH 80                          // 32 halves = 64B data + 16B pad
#define A_BYTES (BM * PITCH)              // 10240
#define B_BYTES (BN * PITCH)              // 10240
#define BOFF    (ASTG * A_BYTES)          // 30720
#define SM_TOTAL (BOFF + 2 * B_BYTES)     // 51200

template<int KTOT, bool RELU, typename OutT>
__global__ void __launch_bounds__(256, 2)
k_gemm(const __half* __restrict__ A,      // [slots, KTOT] fp16
       const float* __restrict__ B32,     // [NEXP*n_total, KTOT] fp32 weights
       const float* __restrict__ bias,
       OutT* __restrict__ C,              // [slots, n_total]
       int n_total) {
    constexpr int NC = KTOT / BK;

    int e = blockIdx.z;
    int cnt = g_cnt[e];
    int m0 = blockIdx.y * BM;
    if (m0 >= cnt) return;
    int base = g_off[e];
    int n0 = blockIdx.x * BN;
    int mrem = cnt - m0;

    extern __shared__ char smc[];
    uint32_t sb = smem_u32(smc);
    int tid = threadIdx.x;
    int wid = tid >> 5, lane = tid & 31;
    int gp = lane >> 2, tg = lane & 3;
    int wm = (wid & 1) * 64;          // warp M offset
    int wn = (wid >> 1) * 32;         // warp N offset

    const __half* Ab = A + (size_t)(base + m0) * KTOT;
    const float* Bb = B32 + ((size_t)e * n_total + n0) * KTOT;

    // A loader (cp.async): 512 16B tasks, 2/thread. row = t>>2, chunk = t&3
    int ar0 = tid >> 2, ac0 = tid & 3;
    int ar1 = (tid + 256) >> 2, ac1 = (tid + 256) & 3;
    auto loadA = [&](int c, int stg) {
        int k0 = c * BK;
        cp16(sb + stg * A_BYTES + ar0 * PITCH + ac0 * 16,
             Ab + (size_t)ar0 * KTOT + k0 + ac0 * 8, ar0 < mrem);
        cp16(sb + stg * A_BYTES + ar1 * PITCH + ac1 * 16,
             Ab + (size_t)ar1 * KTOT + k0 + ac1 * 8, ar1 < mrem);
    };

    // B loader: 128 rows x 32 floats; 2 threads/row, 16 floats each
    float4 breg[4];
    int blr = tid >> 1, blc = tid & 1;
    auto ldgB = [&](int c) {
        const float* p = Bb + (size_t)blr * KTOT + c * BK + blc * 16;
        breg[0] = __ldg((const float4*)p);
        breg[1] = __ldg((const float4*)(p + 4));
        breg[2] = __ldg((const float4*)(p + 8));
        breg[3] = __ldg((const float4*)(p + 12));
    };
    auto stsB = [&](int buf) {
        __half2 h[8];
        #pragma unroll
        for (int i = 0; i < 4; i++) {
            h[i * 2 + 0] = __floats2half2_rn(breg[i].x, breg[i].y);
            h[i * 2 + 1] = __floats2half2_rn(breg[i].z, breg[i].w);
        }
        char* d = smc + BOFF + buf * B_BYTES + blr * PITCH + blc * 32;
        *(uint4*)d = *(uint4*)h;
        *(uint4*)(d + 16) = *(uint4*)(h + 4);
    };

    // per-lane ldmatrix offsets (k-sub step adds ks*32 bytes)
    int m4 = lane >> 3, ri = lane & 7;
    uint32_t a_off[4], b_off[2];
    #pragma unroll
    for (int mi = 0; mi < 4; mi++)
        a_off[mi] = (uint32_t)((wm + mi * 16 + (m4 & 1) * 8 + ri) * PITCH + (m4 >> 1) * 16);
    #pragma unroll
    for (int nj = 0; nj < 2; nj++)
        b_off[nj] = (uint32_t)(BOFF + (wn + nj * 16 + (m4 >> 1) * 8 + ri) * PITCH + (m4 & 1) * 16);

    float acc[4][4][4];
    #pragma unroll
    for (int i = 0; i < 4; i++)
        #pragma unroll
        for (int j = 0; j < 4; j++)
            #pragma unroll
            for (int q = 0; q < 4; q++) acc[i][j][q] = 0.f;

    // prologue
    ldgB(0);
    #pragma unroll
    for (int s = 0; s < ASTG - 1; s++) { loadA(s, s); CP_COMMIT(); }
    stsB(0);
    ldgB(1);

    #pragma unroll 1
    for (int c = 0; c < NC; c++) {
        CP_WAIT(ASTG - 2);
        __syncthreads();                       // A stage c ready; B buf (c&1) visible

        if (c + ASTG - 1 < NC) loadA(c + ASTG - 1, (c + ASTG - 1) % ASTG);
        CP_COMMIT();

        uint32_t ast = sb + (c % ASTG) * A_BYTES;
        uint32_t bst = (c & 1) * B_BYTES;

        #pragma unroll
        for (int ks = 0; ks < 2; ks++) {       // two k16 sub-steps, frags reused
            uint32_t af[4][4], bf[2][4];
            #pragma unroll
            for (int mi = 0; mi < 4; mi++) ldsm_x4(af[mi], ast + a_off[mi] + ks * 32);
            #pragma unroll
            for (int nj = 0; nj < 2; nj++) ldsm_x4(bf[nj], sb + bst + b_off[nj] + ks * 32);
            #pragma unroll
            for (int mi = 0; mi < 4; mi++)
                #pragma unroll
                for (int ni = 0; ni < 4; ni++)
                    mma_f16(acc[mi][ni], af[mi], &bf[ni >> 1][(ni & 1) * 2]);
        }

        if (c + 1 < NC) stsB((c + 1) & 1);     // cvt+store B for next iter
        if (c + 2 < NC) ldgB(c + 2);           // prefetch B fp32 (~1 iter cover)
    }

    // epilogue: bias (+relu), store
    const float* brow = bias + (size_t)e * n_total + n0;
    #pragma unroll
    for (int ni = 0; ni < 4; ni++) {
        int col = wn + ni * 8 + tg * 2;
        float b0 = brow[col], b1 = brow[col + 1];
        #pragma unroll
        for (int mi = 0; mi < 4; mi++) {
            int r0 = wm + mi * 16 + gp;
            float v0 = acc[mi][ni][0] + b0, v1 = acc[mi][ni][1] + b1;
            float v2 = acc[mi][ni][2] + b0, v3 = acc[mi][ni][3] + b1;
            if (RELU) {
                v0 = fmaxf(v0, 0.f); v1 = fmaxf(v1, 0.f);
                v2 = fmaxf(v2, 0.f); v3 = fmaxf(v3, 0.f);
            }
            if (r0 < mrem) {
                OutT* cr = C + (size_t)(base + m0 + r0) * n_total + n0 + col;
                if constexpr (sizeof(OutT) == 2) {
                    *(__half2*)cr = __floats2half2_rn(v0, v1);
                } else { cr[0] = v0; cr[1] = v1; }
            }
            if (r0 + 8 < mrem) {
                OutT* cr = C + (size_t)(base + m0 + r0 + 8) * n_total + n0 + col;
                if constexpr (sizeof(OutT) == 2) {
                    *(__half2*)cr = __floats2half2_rn(v2, v3);
                } else { cr[0] = v2; cr[1] = v3; }
            }
        }
    }
}

// out[t] = w0 * y[slot0] + w1 * y[slot1]
__global__ void k_combine(float* __restrict__ out) {
    int t = blockIdx.x;
    int d4 = threadIdx.x * 4;
    int s0 = g_tok_slot[t * 2 + 0], s1 = g_tok_slot[t * 2 + 1];
    float w0 = g_tok_w[t * 2 + 0],  w1 = g_tok_w[t * 2 + 1];
    float4 y0 = *(const float4*)(g_y + (size_t)s0 * DM + d4);
    float4 y1 = *(const float4*)(g_y + (size_t)s1 * DM + d4);
    float4 r;
    r.x = w0 * y0.x + w1 * y1.x;  r.y = w0 * y0.y + w1 * y1.y;
    r.z = w0 * y0.z + w1 * y1.z;  r.w = w0 * y0.w + w1 * y1.w;
    *(float4*)(out + (size_t)t * DM + d4) = r;
}

// ---------------- launch ----------------
extern "C" void kernel_launch(void* const* d_in, const int* in_sizes, int n_in,
                              void* d_out, int out_size) {
    const float* x  = (const float*)d_in[0];
    const float* gw = (const float*)d_in[1];
    const float* w1 = (const float*)d_in[2];
    const float* b1 = (const float*)d_in[3];
    const float* w2 = (const float*)d_in[4];
    const float* b2 = (const float*)d_in[5];
    float* out = (float*)d_out;

    cudaFuncSetAttribute((const void*)k_gemm<DM, true, __half>,
                         cudaFuncAttributeMaxDynamicSharedMemorySize, SM_TOTAL);
    cudaFuncSetAttribute((const void*)k_gemm<HID, false, float>,
                         cudaFuncAttributeMaxDynamicSharedMemorySize, SM_TOTAL);

    __half* xgh; cudaGetSymbolAddress((void**)&xgh, g_xgh);
    __half* hh;  cudaGetSymbolAddress((void**)&hh,  g_h);
    float*  yy;  cudaGetSymbolAddress((void**)&yy,  g_y);

    k_router<<<NTOK / 8, 256>>>(x, gw);
    k_scan<<<1, 256>>>();
    k_slotgather<<<NPAIRS, 256>>>(x);
    // GEMM1: [slots,1024]h x w1[e][4096,1024]^T (fp32, fused cvt) -> g_h fp16, bias+relu
    k_gemm<DM, true, __half>
        <<<dim3(HID / BN, NPAIRS / BM, NEXP), 256, SM_TOTAL>>>(xgh, w1, b1, hh, HID);
    // GEMM2: [slots,4096]h x w2[e][1024,4096]^T (fp32, fused cvt) -> g_y fp32, bias
    k_gemm<HID, false, float>
        <<<dim3(DM / BN, NPAIRS / BM, NEXP), 256, SM_TOTAL>>>(hh, w2, b2, yy, DM);
    k_combine<<<NTOK, 256>>>(out);
}